// round 15
// baseline (speedup 1.0000x reference)
#include <cuda_runtime.h>
#include <cuda_fp16.h>
#include <math.h>

// ---------------------------------------------------------------------------
// Problem constants
// ---------------------------------------------------------------------------
#define BB   128      // batch
#define SS   336      // src seq len
#define IND  64       // encoder input dim
#define HH   1024     // hidden
#define TT   96       // target len
#define XDIM 1025     // decoder logical input dim (OUT + H)
#define XSTR 1088     // padded decoder input stride (34*32; float4-aligned rows)

typedef unsigned long long ull;

// ---------------------------------------------------------------------------
// Scratch (device globals: allocation-free, graph-capture safe)
// ---------------------------------------------------------------------------
__device__ float  g_h[2][BB * HH];
__device__ float  g_c[2][BB * HH];
__device__ __half g_ench[(size_t)BB * SS * HH];   // fp16 encoder cache (88 MB)
__device__ float  g_qpart[4][BB * HH];            // K-split partials of q
__device__ float  g_x[BB * XSTR];                 // decoder input [prev_y, ctx, 0-pad]

// Per-launch transposed weights WT[k][4096], fp32, zero-padded rows k>=kreal.
// Column layout: c = blk*32 + gate*8 + unit  (CTA 'blk' reads 32 contiguous cols)
__device__ float g_WTeih[64   * 4096];
__device__ float g_WTehh[1024 * 4096];
__device__ float g_WTdih[XSTR * 4096];
__device__ float g_WTdhh[1024 * 4096];

__global__ void init_kernel() {
    int i = blockIdx.x * blockDim.x + threadIdx.x;
    if (i < BB * HH) { g_h[0][i] = 0.f; g_c[0][i] = 0.f; }
    if (i < BB * XSTR) g_x[i] = 0.f;
}

// W [4096 x kreal] row-major  ->  WT [kpad x 4096], CTA-grouped columns
__global__ void transw_kernel(const float* __restrict__ src, int kreal, int kpad,
                              float* __restrict__ dst)
{
    for (long i = blockIdx.x * (long)blockDim.x + threadIdx.x;
         i < (long)kpad * 4096; i += (long)gridDim.x * blockDim.x) {
        int k = (int)(i >> 12);
        int c = (int)(i & 4095);
        int blk = c >> 5, cc = c & 31, g = cc >> 3, u = cc & 7;
        int row = g * HH + blk * 8 + u;
        dst[i] = (k < kreal) ? src[(size_t)row * kreal + k] : 0.f;
    }
}

__device__ __forceinline__ float sigf(float v) { return 1.f / (1.f + expf(-v)); }

// ---- packed fp32x2 helpers (Blackwell FFMA2; ptxas won't emit from C++) ----
__device__ __forceinline__ ull pk2(float x, float y) {
    ull r; asm("mov.b64 %0, {%1,%2};" : "=l"(r) : "f"(x), "f"(y)); return r;
}
__device__ __forceinline__ void fma2(ull& d, ull a, ull b) {
    asm("fma.rn.f32x2 %0, %1, %2, %0;" : "+l"(d) : "l"(a), "l"(b));
}
__device__ __forceinline__ void unpk2(ull v, float& lo, float& hi) {
    asm("mov.b64 {%0,%1}, %2;" : "=f"(lo), "=f"(hi) : "l"(v));
}

// ---------------------------------------------------------------------------
// A-tile loader: 128 rows x 32 k -> 16 floats/thread
// (rows tmA+32*ib, k = k0 + 4*kg + {0..3}).  All accesses float4 (padded).
// ---------------------------------------------------------------------------
__device__ __forceinline__ void load_a(
    int t, int ntx,
    const float* __restrict__ x, int x_stride,
    const float* __restrict__ h_in,
    int tmA, int kg, float ra[16])
{
    const float* __restrict__ src = (t < ntx) ? x : h_in;
    const int    stride           = (t < ntx) ? x_stride : HH;
    const int    k0               = ((t < ntx) ? t : (t - ntx)) * 32;
#pragma unroll
    for (int ib = 0; ib < 4; ++ib) {
        float4 v = *(const float4*)(src + (size_t)(tmA + 32 * ib) * stride + k0 + 4 * kg);
        ra[ib*4+0] = v.x; ra[ib*4+1] = v.y; ra[ib*4+2] = v.z; ra[ib*4+3] = v.w;
    }
}

// ---------------------------------------------------------------------------
// Fused LSTM step, v5: A in smem (transposed), B via uniform LDG.128 broadcast
// from per-launch transposed WT (L2-resident) — smem crossbar decongested.
// Grid = 128 CTAs x 256 threads; CTA owns units [8*blk,8*blk+8) over 4 gates
// (32 cols of the [128 x 4096] gate matrix).  Thread = 2 rows x 8 cols ->
// 8 packed FFMA2 accumulators.
// Inner loop / kk: 2 LDS.32(A) + 2 pack + 2 LDG.128(WT bcast) + 8 FFMA2.
// Per SMSP (2 warps): issue 28, FFMA2 port 32 (bound), LDG 16, crossbar 16/SM.
// ---------------------------------------------------------------------------
__global__ __launch_bounds__(256)
void lstm_step_kernel(const float* __restrict__ x, int x_stride, int ntx,
                      const float* __restrict__ WTih,
                      const float* __restrict__ h_in,
                      const float* __restrict__ WThh,
                      const float* __restrict__ b_ih,
                      const float* __restrict__ b_hh,
                      const float* __restrict__ c_in,
                      float* __restrict__ h_out,
                      float* __restrict__ c_out,
                      __half* __restrict__ enc_out)   // nullable; pre-offset by t*H
{
    // GEMM phase: sAt[kk][row] (32*128); epilogue: sG[row][33] (128*33)
    __shared__ __align__(16) float sPool[4352];

    const int tid = threadIdx.x;
    const int j0  = blockIdx.x * 8;

    // compute map: 2 rows x 8 cols
    const int rr = tid & 63;
    const int gq = tid >> 6;          // gate group 0..3
    const int cb = gq * 8;

    // A-load map
    const int tmA = tid & 31, kg = tid >> 5;

    // B column base within WT row
    const int wcol = blockIdx.x * 32 + cb;

    const int nt = ntx + 32;

    float ra[16];
    ull acc[2][4];
#pragma unroll
    for (int i = 0; i < 2; ++i)
#pragma unroll
        for (int u = 0; u < 4; ++u) acc[i][u] = 0ull;

    load_a(0, ntx, x, x_stride, h_in, tmA, kg, ra);

    for (int t = 0; t < nt; ++t) {
        __syncthreads();                       // previous tile's compute done
#pragma unroll
        for (int ib = 0; ib < 4; ++ib)
#pragma unroll
            for (int j = 0; j < 4; ++j)
                sPool[(4 * kg + j) * 128 + tmA + 32 * ib] = ra[ib * 4 + j];
        __syncthreads();

        if (t + 1 < nt)                        // A prefetch overlaps compute
            load_a(t + 1, ntx, x, x_stride, h_in, tmA, kg, ra);

        // B row base for this tile (fp32 WT, uniform across warp -> broadcast)
        const float* __restrict__ wt =
            (t < ntx) ? (WTih + (size_t)(t * 32) * 4096 + wcol)
                      : (WThh + (size_t)((t - ntx) * 32) * 4096 + wcol);

#pragma unroll 4
        for (int kk = 0; kk < 32; ++kk) {
            ulonglong2 W0 = *(const ulonglong2*)(wt + (size_t)kk * 4096);
            ulonglong2 W1 = *(const ulonglong2*)(wt + (size_t)kk * 4096 + 4);
            float a0 = sPool[kk * 128 + rr];
            float a1 = sPool[kk * 128 + rr + 64];
            ull A0 = pk2(a0, a0);
            ull A1 = pk2(a1, a1);
            fma2(acc[0][0], A0, W0.x);
            fma2(acc[0][1], A0, W0.y);
            fma2(acc[0][2], A0, W1.x);
            fma2(acc[0][3], A0, W1.y);
            fma2(acc[1][0], A1, W0.x);
            fma2(acc[1][1], A1, W0.y);
            fma2(acc[1][2], A1, W1.x);
            fma2(acc[1][3], A1, W1.y);
        }
    }

    // -------- stage gates to smem: sG[row][33] (reuse pool) --------
    __syncthreads();
    float* sG = sPool;
#pragma unroll
    for (int i = 0; i < 2; ++i) {
        const int row = rr + 64 * i;
#pragma unroll
        for (int u = 0; u < 4; ++u) {
            float lo, hi; unpk2(acc[i][u], lo, hi);
            sG[row * 33 + cb + 2 * u]     = lo;
            sG[row * 33 + cb + 2 * u + 1] = hi;
        }
    }
    __syncthreads();

    // -------- pointwise LSTM cell (i,f,g,o order); 32 rows x 8 units map ----
    {
        const int tm = tid & 31, tn = tid >> 5;
        const int u  = j0 + tn;
        const float bi = b_ih[u]          + b_hh[u];
        const float bf = b_ih[HH + u]     + b_hh[HH + u];
        const float bg = b_ih[2 * HH + u] + b_hh[2 * HH + u];
        const float bo = b_ih[3 * HH + u] + b_hh[3 * HH + u];
#pragma unroll
        for (int i = 0; i < 4; ++i) {
            const int b = tm + 32 * i;
            float gi = sG[b * 33 + tn]      + bi;
            float gf = sG[b * 33 + 8 + tn]  + bf;
            float gg = sG[b * 33 + 16 + tn] + bg;
            float go = sG[b * 33 + 24 + tn] + bo;
            float co = c_in[(size_t)b * HH + u];
            float cn = sigf(gf) * co + sigf(gi) * tanhf(gg);
            float hn = sigf(go) * tanhf(cn);
            h_out[(size_t)b * HH + u] = hn;
            c_out[(size_t)b * HH + u] = cn;
            if (enc_out) enc_out[(size_t)b * SS * HH + u] = __float2half(hn);
        }
    }
}

// ---------------------------------------------------------------------------
// D1: q = h @ attn_W^T, K-split x4 into g_qpart.
// ---------------------------------------------------------------------------
__global__ __launch_bounds__(256)
void qgemm_kernel(const float* __restrict__ h,
                  const float* __restrict__ attnW,
                  float* __restrict__ qpart)
{
    __shared__ float sA[128][33];
    __shared__ float sB[32][33];
    const int tid = threadIdx.x;
    const int tm  = tid & 31;
    const int tn  = tid >> 5;
    const int ks  = blockIdx.x >> 5;
    const int n0  = (blockIdx.x & 31) << 5;

    float acc[4][4];
#pragma unroll
    for (int i = 0; i < 4; ++i)
#pragma unroll
        for (int j = 0; j < 4; ++j) acc[i][j] = 0.f;

    for (int tile = 0; tile < 8; ++tile) {
        const int k0 = ks * 256 + tile * 32;
#pragma unroll
        for (int rr = 0; rr < 16; ++rr) {
            int idx = tid + rr * 256;
            int b = idx >> 5, kk = idx & 31;
            sA[b][kk] = h[(size_t)b * HH + k0 + kk];
        }
#pragma unroll
        for (int rr = 0; rr < 4; ++rr) {
            int idx = tid + rr * 256;
            int c = idx >> 5, kk = idx & 31;
            sB[c][kk] = attnW[(size_t)(n0 + c) * HH + k0 + kk];
        }
        __syncthreads();
#pragma unroll
        for (int kk = 0; kk < 32; ++kk) {
            float a0 = sA[tm][kk], a1 = sA[tm + 32][kk];
            float a2 = sA[tm + 64][kk], a3 = sA[tm + 96][kk];
            float w0 = sB[tn][kk],      w1 = sB[tn + 8][kk];
            float w2 = sB[tn + 16][kk], w3 = sB[tn + 24][kk];
            acc[0][0] += a0 * w0; acc[0][1] += a0 * w1; acc[0][2] += a0 * w2; acc[0][3] += a0 * w3;
            acc[1][0] += a1 * w0; acc[1][1] += a1 * w1; acc[1][2] += a1 * w2; acc[1][3] += a1 * w3;
            acc[2][0] += a2 * w0; acc[2][1] += a2 * w1; acc[2][2] += a2 * w2; acc[2][3] += a2 * w3;
            acc[3][0] += a3 * w0; acc[3][1] += a3 * w1; acc[3][2] += a3 * w2; acc[3][3] += a3 * w3;
        }
        __syncthreads();
    }

    float* qo = qpart + (size_t)ks * BB * HH;
#pragma unroll
    for (int i = 0; i < 4; ++i)
#pragma unroll
        for (int j = 0; j < 4; ++j)
            qo[(size_t)(tm + 32 * i) * HH + n0 + tn + 8 * j] = acc[i][j];
}

// ---------------------------------------------------------------------------
// D2: Luong attention over fp16 encoder cache (verified path from R9/R11).
// ---------------------------------------------------------------------------
__global__ __launch_bounds__(512)
void attn_kernel(const float* __restrict__ qpart,
                 const __half* __restrict__ enc,
                 float* __restrict__ xbuf)
{
    const int b    = blockIdx.x;
    const int tid  = threadIdx.x;
    const int w    = tid >> 5;
    const int lane = tid & 31;

    __shared__ __align__(16) float sm_ctx[8][1024];
    __shared__ float sm_m[16], sm_d[16];

    float4 q4[8]; float ctx[32];
    const float4* p0 = (const float4*)(qpart + 0 * (size_t)BB * HH + (size_t)b * HH);
    const float4* p1 = (const float4*)(qpart + 1 * (size_t)BB * HH + (size_t)b * HH);
    const float4* p2 = (const float4*)(qpart + 2 * (size_t)BB * HH + (size_t)b * HH);
    const float4* p3 = (const float4*)(qpart + 3 * (size_t)BB * HH + (size_t)b * HH);
#pragma unroll
    for (int j = 0; j < 4; ++j) {
        int i0 = 2 * lane + 64 * j;
#pragma unroll
        for (int h2 = 0; h2 < 2; ++h2) {
            float4 a = p0[i0 + h2], c = p1[i0 + h2], d2 = p2[i0 + h2], e2 = p3[i0 + h2];
            q4[2 * j + h2].x = a.x + c.x + d2.x + e2.x;
            q4[2 * j + h2].y = a.y + c.y + d2.y + e2.y;
            q4[2 * j + h2].z = a.z + c.z + d2.z + e2.z;
            q4[2 * j + h2].w = a.w + c.w + d2.w + e2.w;
        }
    }
#pragma unroll
    for (int i = 0; i < 32; ++i) ctx[i] = 0.f;

    float m = -1e30f, d = 0.f;
    const uint4* erow = (const uint4*)(enc + (size_t)b * SS * HH);

    for (int it = 0; it < SS / 16; ++it) {
        const int s = w + 16 * it;
        const uint4* er = erow + (size_t)s * (HH / 8);
        uint4 eh[4];
#pragma unroll
        for (int j = 0; j < 4; ++j) eh[j] = er[lane + 32 * j];

        float ef[32];
#pragma unroll
        for (int j = 0; j < 4; ++j) {
            const __half2* hp = (const __half2*)&eh[j];
#pragma unroll
            for (int t2 = 0; t2 < 4; ++t2) {
                float2 f = __half22float2(hp[t2]);
                ef[8 * j + 2 * t2]     = f.x;
                ef[8 * j + 2 * t2 + 1] = f.y;
            }
        }

        float p = 0.f;
#pragma unroll
        for (int j = 0; j < 8; ++j)
            p += q4[j].x * ef[4 * j]     + q4[j].y * ef[4 * j + 1] +
                 q4[j].z * ef[4 * j + 2] + q4[j].w * ef[4 * j + 3];
#pragma unroll
        for (int off = 16; off >= 1; off >>= 1)
            p += __shfl_xor_sync(0xffffffffu, p, off);

        float mn = fmaxf(m, p);
        float sc = expf(m - mn);
        float wv = expf(p - mn);
        d = d * sc + wv;
#pragma unroll
        for (int i = 0; i < 32; ++i) ctx[i] = ctx[i] * sc + wv * ef[i];
        m = mn;
    }

    if (w >= 8) {
#pragma unroll
        for (int j = 0; j < 4; ++j) {
            ((float4*)sm_ctx[w - 8])[2 * lane + 64 * j]     = make_float4(ctx[8*j],   ctx[8*j+1], ctx[8*j+2], ctx[8*j+3]);
            ((float4*)sm_ctx[w - 8])[2 * lane + 64 * j + 1] = make_float4(ctx[8*j+4], ctx[8*j+5], ctx[8*j+6], ctx[8*j+7]);
        }
    }
    if (lane == 0) { sm_m[w] = m; sm_d[w] = d; }
    __syncthreads();
    if (w < 8) {
        float m2 = sm_m[w + 8], d2 = sm_d[w + 8];
        float mn = fmaxf(m, m2);
        float s1 = expf(m - mn), s2 = expf(m2 - mn);
        d = d * s1 + d2 * s2;
#pragma unroll
        for (int j = 0; j < 4; ++j) {
            float4 v0 = ((float4*)sm_ctx[w])[2 * lane + 64 * j];
            float4 v1 = ((float4*)sm_ctx[w])[2 * lane + 64 * j + 1];
            ctx[8*j]   = ctx[8*j]   * s1 + v0.x * s2;
            ctx[8*j+1] = ctx[8*j+1] * s1 + v0.y * s2;
            ctx[8*j+2] = ctx[8*j+2] * s1 + v0.z * s2;
            ctx[8*j+3] = ctx[8*j+3] * s1 + v0.w * s2;
            ctx[8*j+4] = ctx[8*j+4] * s1 + v1.x * s2;
            ctx[8*j+5] = ctx[8*j+5] * s1 + v1.y * s2;
            ctx[8*j+6] = ctx[8*j+6] * s1 + v1.z * s2;
            ctx[8*j+7] = ctx[8*j+7] * s1 + v1.w * s2;
        }
        m = mn;
#pragma unroll
        for (int j = 0; j < 4; ++j) {
            ((float4*)sm_ctx[w])[2 * lane + 64 * j]     = make_float4(ctx[8*j],   ctx[8*j+1], ctx[8*j+2], ctx[8*j+3]);
            ((float4*)sm_ctx[w])[2 * lane + 64 * j + 1] = make_float4(ctx[8*j+4], ctx[8*j+5], ctx[8*j+6], ctx[8*j+7]);
        }
        if (lane == 0) { sm_m[w] = m; sm_d[w] = d; }
    }
    __syncthreads();

    float mstar = sm_m[0];
#pragma unroll
    for (int ww = 1; ww < 8; ++ww) mstar = fmaxf(mstar, sm_m[ww]);
    float ew[8], dtot = 0.f;
#pragma unroll
    for (int ww = 0; ww < 8; ++ww) { ew[ww] = expf(sm_m[ww] - mstar); dtot += sm_d[ww] * ew[ww]; }
    const float inv = 1.f / dtot;

    float cx0 = 0.f, cx1 = 0.f;
#pragma unroll
    for (int ww = 0; ww < 8; ++ww) {
        float2 v = ((float2*)sm_ctx[ww])[tid];
        cx0 += v.x * ew[ww]; cx1 += v.y * ew[ww];
    }
    float* xo = xbuf + (size_t)b * XSTR + 1 + 2 * tid;
    xo[0] = cx0 * inv; xo[1] = cx1 * inv;
}

// ---------------------------------------------------------------------------
// D4: pred = h @ fc_W^T + fc_b (OUT=1); writes out[b,t] and prev_y slot.
// ---------------------------------------------------------------------------
__global__ void fc_kernel(const float* __restrict__ h,
                          const float* __restrict__ fcW,
                          const float* __restrict__ fcb,
                          float* __restrict__ out,
                          float* __restrict__ xbuf, int t)
{
    const int b = blockIdx.x;
    const int lane = threadIdx.x;
    float s = 0.f;
#pragma unroll
    for (int i = 0; i < 32; ++i) {
        int k = lane + 32 * i;
        s += h[(size_t)b * HH + k] * fcW[k];
    }
#pragma unroll
    for (int off = 16; off >= 1; off >>= 1)
        s += __shfl_xor_sync(0xffffffffu, s, off);
    if (lane == 0) {
        float p = s + fcb[0];
        out[(size_t)b * TT + t] = p;
        xbuf[(size_t)b * XSTR] = p;
    }
}

// ---------------------------------------------------------------------------
// kernel_launch: graph-capturable sequence (default stream).
// ---------------------------------------------------------------------------
extern "C" void kernel_launch(void* const* d_in, const int* in_sizes, int n_in,
                              void* d_out, int out_size)
{
    const float* src   = (const float*)d_in[0];
    const float* eWih  = (const float*)d_in[1];
    const float* eWhh  = (const float*)d_in[2];
    const float* ebih  = (const float*)d_in[3];
    const float* ebhh  = (const float*)d_in[4];
    const float* dWih  = (const float*)d_in[5];
    const float* dWhh  = (const float*)d_in[6];
    const float* dbih  = (const float*)d_in[7];
    const float* dbhh  = (const float*)d_in[8];
    const float* attnW = (const float*)d_in[9];
    const float* fcW   = (const float*)d_in[10];
    const float* fcb   = (const float*)d_in[11];
    float* out = (float*)d_out;

    float *hb, *cb, *qp, *xb, *wteih, *wtehh, *wtdih, *wtdhh;
    __half* ench;
    cudaGetSymbolAddress((void**)&hb,    g_h);
    cudaGetSymbolAddress((void**)&cb,    g_c);
    cudaGetSymbolAddress((void**)&ench,  g_ench);
    cudaGetSymbolAddress((void**)&qp,    g_qpart);
    cudaGetSymbolAddress((void**)&xb,    g_x);
    cudaGetSymbolAddress((void**)&wteih, g_WTeih);
    cudaGetSymbolAddress((void**)&wtehh, g_WTehh);
    cudaGetSymbolAddress((void**)&wtdih, g_WTdih);
    cudaGetSymbolAddress((void**)&wtdhh, g_WTdhh);

    float* hbuf[2] = { hb, hb + BB * HH };
    float* cbuf[2] = { cb, cb + BB * HH };

    // one-time per launch: transpose weights into CTA-grouped WT layout
    transw_kernel<<<2048, 256>>>(eWih, 64,   64,   wteih);
    transw_kernel<<<2048, 256>>>(eWhh, 1024, 1024, wtehh);
    transw_kernel<<<2048, 256>>>(dWih, XDIM, XSTR, wtdih);
    transw_kernel<<<2048, 256>>>(dWhh, 1024, 1024, wtdhh);
    init_kernel<<<(BB * XSTR + 255) / 256, 256>>>();

    // ---- encoder: 336 steps (ntx = 64/32 = 2) ----
    for (int t = 0; t < SS; ++t) {
        int p = t & 1;
        lstm_step_kernel<<<HH / 8, 256>>>(
            src + (size_t)t * IND, SS * IND, /*ntx=*/2, wteih,
            hbuf[p], wtehh, ebih, ebhh, cbuf[p],
            hbuf[1 - p], cbuf[1 - p],
            ench + (size_t)t * HH);
    }

    // ---- decoder: 96 steps (ntx = 1088/32 = 34; x fully padded) ----
    for (int t = 0; t < TT; ++t) {
        int p = t & 1;
        qgemm_kernel<<<128, 256>>>(hbuf[p], attnW, qp);
        attn_kernel<<<BB, 512>>>(qp, ench, xb);
        lstm_step_kernel<<<HH / 8, 256>>>(
            xb, XSTR, /*ntx=*/34, wtdih,
            hbuf[p], wtdhh, dbih, dbhh, cbuf[p],
            hbuf[1 - p], cbuf[1 - p],
            (__half*)nullptr);
        fc_kernel<<<BB, 32>>>(hbuf[1 - p], fcW, fcb, out, xb, t);
    }
}

// round 16
// speedup vs baseline: 3.3862x; 3.3862x over previous
#include <cuda_runtime.h>
#include <cuda_fp16.h>
#include <math.h>

// ---------------------------------------------------------------------------
// Problem constants
// ---------------------------------------------------------------------------
#define BB   128      // batch
#define SS   336      // src seq len
#define IND  64       // encoder input dim
#define HH   1024     // hidden
#define TT   96       // target len
#define XDIM 1025     // decoder logical input dim (OUT + H)
#define XSTR 1088     // padded decoder input stride (34*32; float4-aligned rows)

typedef unsigned long long ull;

// ---------------------------------------------------------------------------
// Scratch (device globals: allocation-free, graph-capture safe)
// ---------------------------------------------------------------------------
__device__ float  g_h[2][BB * HH];
__device__ float  g_c[2][BB * HH];
__device__ __half g_ench[(size_t)BB * SS * HH];   // fp16 encoder cache (88 MB)
__device__ float  g_qpart[4][BB * HH];            // K-split partials of q
__device__ float  g_x[BB * XSTR];                 // decoder input [prev_y, ctx, 0-pad]
__device__ float  g_Wdih_pad[4096 * XSTR];        // dec W_ih zero-padded to XSTR cols

__global__ void init_kernel() {
    int i = blockIdx.x * blockDim.x + threadIdx.x;
    if (i < BB * HH) { g_h[0][i] = 0.f; g_c[0][i] = 0.f; }
    if (i < BB * XSTR) g_x[i] = 0.f;
}

// Pad dec W_ih: [4096 x 1025] -> [4096 x XSTR] (row-major, zero tail)
__global__ void padw_kernel(const float* __restrict__ src, float* __restrict__ dst)
{
    for (long i = blockIdx.x * (long)blockDim.x + threadIdx.x;
         i < (long)4096 * XSTR; i += (long)gridDim.x * blockDim.x) {
        int r = (int)(i / XSTR), k = (int)(i - (long)r * XSTR);
        dst[i] = (k < XDIM) ? src[(size_t)r * XDIM + k] : 0.f;
    }
}

__device__ __forceinline__ float sigf(float v) { return 1.f / (1.f + expf(-v)); }

// ---- packed fp32x2 helpers (Blackwell FFMA2; ptxas won't emit from C++) ----
__device__ __forceinline__ ull pk2(float x, float y) {
    ull r; asm("mov.b64 %0, {%1,%2};" : "=l"(r) : "f"(x), "f"(y)); return r;
}
__device__ __forceinline__ void fma2(ull& d, ull a, ull b) {
    asm("fma.rn.f32x2 %0, %1, %2, %0;" : "+l"(d) : "l"(a), "l"(b));
}
__device__ __forceinline__ void unpk2(ull v, float& lo, float& hi) {
    asm("mov.b64 {%0,%1}, %2;" : "=f"(lo), "=f"(hi) : "l"(v));
}

// ---------------------------------------------------------------------------
// Register-staged tile loader (all paths vectored; inputs pre-padded).
// A: 128 rows x 32 k -> 16 floats/thread (rows tmA+32*ib, k = k0+4*kg+{0..3})
// B: 32 cols x 32 k  -> 4 floats/thread  (col colB, k = k0+kbB+{0..3})
// ---------------------------------------------------------------------------
__device__ __forceinline__ void load_tile(
    int t, int ntx,
    const float* __restrict__ x, int x_stride, int wk,   // wk = Wih row stride
    const float* __restrict__ Wih,
    const float* __restrict__ h_in,
    const float* __restrict__ Whh,
    int tmA, int kg, int rowB, int kbB,
    float ra[16], float rb[4])
{
    if (t < ntx) {
        const int k0 = t * 32;
#pragma unroll
        for (int ib = 0; ib < 4; ++ib) {
            float4 v = *(const float4*)(x + (size_t)(tmA + 32 * ib) * x_stride + k0 + 4 * kg);
            ra[ib*4+0] = v.x; ra[ib*4+1] = v.y; ra[ib*4+2] = v.z; ra[ib*4+3] = v.w;
        }
        float4 wv = *(const float4*)(Wih + (size_t)rowB * wk + k0 + kbB);
        rb[0] = wv.x; rb[1] = wv.y; rb[2] = wv.z; rb[3] = wv.w;
    } else {
        const int k0 = (t - ntx) * 32;
#pragma unroll
        for (int ib = 0; ib < 4; ++ib) {
            float4 v = *(const float4*)(h_in + (size_t)(tmA + 32 * ib) * HH + k0 + 4 * kg);
            ra[ib*4+0] = v.x; ra[ib*4+1] = v.y; ra[ib*4+2] = v.z; ra[ib*4+3] = v.w;
        }
        float4 wv = *(const float4*)(Whh + (size_t)rowB * HH + k0 + kbB);
        rb[0] = wv.x; rb[1] = wv.y; rb[2] = wv.z; rb[3] = wv.w;
    }
}

// ---------------------------------------------------------------------------
// Fused LSTM step v6 = R6 (67.4us, best) with the sBt alignment bug fixed.
// Grid = 128 CTAs x 256 threads; CTA owns units [8*blk,8*blk+8) over 4 gates.
// Thread = 2 rows x 8 cols -> 8 packed FFMA2 accumulators.
// sBt stride 36 floats: (kk*36+cb)*4 = kk*144 + {0,32,64,96} -> 16B aligned,
// so both W reads are true LDS.128 broadcasts.
// Per kk per warp: 2 LDS.32(A) + 2 pack + 2 LDS.128(W bcast) + 8 FFMA2.
// Crossbar: 4 wavefronts x 8 warps = 32/SM/kk == FMA port 32 cyc/SMSP/kk.
// ---------------------------------------------------------------------------
__global__ __launch_bounds__(256)
void lstm_step_kernel(const float* __restrict__ x, int x_stride, int ntx, int wk,
                      const float* __restrict__ Wih,
                      const float* __restrict__ h_in,
                      const float* __restrict__ Whh,
                      const float* __restrict__ b_ih,
                      const float* __restrict__ b_hh,
                      const float* __restrict__ c_in,
                      float* __restrict__ h_out,
                      float* __restrict__ c_out,
                      __half* __restrict__ enc_out)   // nullable; pre-offset by t*H
{
    __shared__ __align__(16) float sPool[128 * 33]; // GEMM: sAt[kk][b]; epi: sG[b][33]
    __shared__ __align__(16) float sBt[32 * 36];    // [kk][col], stride 36 (16B rows)

    const int tid = threadIdx.x;
    const int j0  = blockIdx.x * 8;

    // load maps
    const int tmA  = tid & 31, kg = tid >> 5;          // A: b-lane, k-group
    const int colB = tid >> 3, kbB = (tid & 7) * 4;    // B: col, k-offset
    const int rowB = (colB >> 3) * HH + j0 + (colB & 7);
    // compute map
    const int rr = tid & 63;          // rows {rr, rr+64}
    const int cb = (tid >> 6) * 8;    // cols {cb .. cb+7} (uniform per warp)

    const int nt = ntx + 32;

    float ra[16], rb[4];
    ull acc[2][4];
#pragma unroll
    for (int i = 0; i < 2; ++i)
#pragma unroll
        for (int u = 0; u < 4; ++u) acc[i][u] = 0ull;

    load_tile(0, ntx, x, x_stride, wk, Wih, h_in, Whh, tmA, kg, rowB, kbB, ra, rb);

    for (int t = 0; t < nt; ++t) {
        __syncthreads();               // previous tile's compute done
#pragma unroll
        for (int ib = 0; ib < 4; ++ib)
#pragma unroll
            for (int j = 0; j < 4; ++j)
                sPool[(4 * kg + j) * 128 + tmA + 32 * ib] = ra[ib * 4 + j];
#pragma unroll
        for (int j = 0; j < 4; ++j)
            sBt[(kbB + j) * 36 + colB] = rb[j];
        __syncthreads();

        if (t + 1 < nt)                // prefetch next tile; latency overlaps compute
            load_tile(t + 1, ntx, x, x_stride, wk, Wih, h_in, Whh,
                      tmA, kg, rowB, kbB, ra, rb);

#pragma unroll 8
        for (int kk = 0; kk < 32; ++kk) {
            float a0 = sPool[kk * 128 + rr];
            float a1 = sPool[kk * 128 + rr + 64];
            ull A0 = pk2(a0, a0);
            ull A1 = pk2(a1, a1);
            ulonglong2 W0 = *(const ulonglong2*)(sBt + kk * 36 + cb);      // LDS.128 bcast
            ulonglong2 W1 = *(const ulonglong2*)(sBt + kk * 36 + cb + 4);  // LDS.128 bcast
            fma2(acc[0][0], A0, W0.x);
            fma2(acc[0][1], A0, W0.y);
            fma2(acc[0][2], A0, W1.x);
            fma2(acc[0][3], A0, W1.y);
            fma2(acc[1][0], A1, W0.x);
            fma2(acc[1][1], A1, W0.y);
            fma2(acc[1][2], A1, W1.x);
            fma2(acc[1][3], A1, W1.y);
        }
    }

    // -------- stage gate values to smem (sG[b][33]) --------
    __syncthreads();
    float* sG = sPool;
#pragma unroll
    for (int i = 0; i < 2; ++i) {
        const int row = rr + 64 * i;
#pragma unroll
        for (int u = 0; u < 4; ++u) {
            float lo, hi; unpk2(acc[i][u], lo, hi);
            sG[row * 33 + cb + 2 * u]     = lo;
            sG[row * 33 + cb + 2 * u + 1] = hi;
        }
    }
    __syncthreads();

    // -------- pointwise LSTM cell (i,f,g,o order) --------
    const int tm = tid & 31, tn = tid >> 5;
    const int u  = j0 + tn;
    const float bi = b_ih[u]          + b_hh[u];
    const float bf = b_ih[HH + u]     + b_hh[HH + u];
    const float bg = b_ih[2 * HH + u] + b_hh[2 * HH + u];
    const float bo = b_ih[3 * HH + u] + b_hh[3 * HH + u];
#pragma unroll
    for (int i = 0; i < 4; ++i) {
        const int b = tm + 32 * i;
        float gi = sG[b * 33 + tn]      + bi;
        float gf = sG[b * 33 + 8 + tn]  + bf;
        float gg = sG[b * 33 + 16 + tn] + bg;
        float go = sG[b * 33 + 24 + tn] + bo;
        float co = c_in[(size_t)b * HH + u];
        float cn = sigf(gf) * co + sigf(gi) * tanhf(gg);
        float hn = sigf(go) * tanhf(cn);
        h_out[(size_t)b * HH + u] = hn;
        c_out[(size_t)b * HH + u] = cn;
        if (enc_out) enc_out[(size_t)b * SS * HH + u] = __float2half(hn);
    }
}

// ---------------------------------------------------------------------------
// D1: q = h @ attn_W^T, K-split x4 into g_qpart (proven path).
// ---------------------------------------------------------------------------
__global__ __launch_bounds__(256)
void qgemm_kernel(const float* __restrict__ h,
                  const float* __restrict__ attnW,
                  float* __restrict__ qpart)
{
    __shared__ float sA[128][33];
    __shared__ float sB[32][33];
    const int tid = threadIdx.x;
    const int tm  = tid & 31;
    const int tn  = tid >> 5;
    const int ks  = blockIdx.x >> 5;
    const int n0  = (blockIdx.x & 31) << 5;

    float acc[4][4];
#pragma unroll
    for (int i = 0; i < 4; ++i)
#pragma unroll
        for (int j = 0; j < 4; ++j) acc[i][j] = 0.f;

    for (int tile = 0; tile < 8; ++tile) {
        const int k0 = ks * 256 + tile * 32;
#pragma unroll
        for (int rr = 0; rr < 16; ++rr) {
            int idx = tid + rr * 256;
            int b = idx >> 5, kk = idx & 31;
            sA[b][kk] = h[(size_t)b * HH + k0 + kk];
        }
#pragma unroll
        for (int rr = 0; rr < 4; ++rr) {
            int idx = tid + rr * 256;
            int c = idx >> 5, kk = idx & 31;
            sB[c][kk] = attnW[(size_t)(n0 + c) * HH + k0 + kk];
        }
        __syncthreads();
#pragma unroll
        for (int kk = 0; kk < 32; ++kk) {
            float a0 = sA[tm][kk], a1 = sA[tm + 32][kk];
            float a2 = sA[tm + 64][kk], a3 = sA[tm + 96][kk];
            float w0 = sB[tn][kk],      w1 = sB[tn + 8][kk];
            float w2 = sB[tn + 16][kk], w3 = sB[tn + 24][kk];
            acc[0][0] += a0 * w0; acc[0][1] += a0 * w1; acc[0][2] += a0 * w2; acc[0][3] += a0 * w3;
            acc[1][0] += a1 * w0; acc[1][1] += a1 * w1; acc[1][2] += a1 * w2; acc[1][3] += a1 * w3;
            acc[2][0] += a2 * w0; acc[2][1] += a2 * w1; acc[2][2] += a2 * w2; acc[2][3] += a2 * w3;
            acc[3][0] += a3 * w0; acc[3][1] += a3 * w1; acc[3][2] += a3 * w2; acc[3][3] += a3 * w3;
        }
        __syncthreads();
    }

    float* qo = qpart + (size_t)ks * BB * HH;
#pragma unroll
    for (int i = 0; i < 4; ++i)
#pragma unroll
        for (int j = 0; j < 4; ++j)
            qo[(size_t)(tm + 32 * i) * HH + n0 + tn + 8 * j] = acc[i][j];
}

// ---------------------------------------------------------------------------
// D2: Luong attention over fp16 encoder cache (proven path, R9/R11/R15).
// ---------------------------------------------------------------------------
__global__ __launch_bounds__(512)
void attn_kernel(const float* __restrict__ qpart,
                 const __half* __restrict__ enc,
                 float* __restrict__ xbuf)
{
    const int b    = blockIdx.x;
    const int tid  = threadIdx.x;
    const int w    = tid >> 5;
    const int lane = tid & 31;

    __shared__ __align__(16) float sm_ctx[8][1024];
    __shared__ float sm_m[16], sm_d[16];

    float4 q4[8]; float ctx[32];
    const float4* p0 = (const float4*)(qpart + 0 * (size_t)BB * HH + (size_t)b * HH);
    const float4* p1 = (const float4*)(qpart + 1 * (size_t)BB * HH + (size_t)b * HH);
    const float4* p2 = (const float4*)(qpart + 2 * (size_t)BB * HH + (size_t)b * HH);
    const float4* p3 = (const float4*)(qpart + 3 * (size_t)BB * HH + (size_t)b * HH);
#pragma unroll
    for (int j = 0; j < 4; ++j) {
        int i0 = 2 * lane + 64 * j;
#pragma unroll
        for (int h2 = 0; h2 < 2; ++h2) {
            float4 a = p0[i0 + h2], c = p1[i0 + h2], d2 = p2[i0 + h2], e2 = p3[i0 + h2];
            q4[2 * j + h2].x = a.x + c.x + d2.x + e2.x;
            q4[2 * j + h2].y = a.y + c.y + d2.y + e2.y;
            q4[2 * j + h2].z = a.z + c.z + d2.z + e2.z;
            q4[2 * j + h2].w = a.w + c.w + d2.w + e2.w;
        }
    }
#pragma unroll
    for (int i = 0; i < 32; ++i) ctx[i] = 0.f;

    float m = -1e30f, d = 0.f;
    const uint4* erow = (const uint4*)(enc + (size_t)b * SS * HH);

    for (int it = 0; it < SS / 16; ++it) {
        const int s = w + 16 * it;
        const uint4* er = erow + (size_t)s * (HH / 8);
        uint4 eh[4];
#pragma unroll
        for (int j = 0; j < 4; ++j) eh[j] = er[lane + 32 * j];

        float ef[32];
#pragma unroll
        for (int j = 0; j < 4; ++j) {
            const __half2* hp = (const __half2*)&eh[j];
#pragma unroll
            for (int t2 = 0; t2 < 4; ++t2) {
                float2 f = __half22float2(hp[t2]);
                ef[8 * j + 2 * t2]     = f.x;
                ef[8 * j + 2 * t2 + 1] = f.y;
            }
        }

        float p = 0.f;
#pragma unroll
        for (int j = 0; j < 8; ++j)
            p += q4[j].x * ef[4 * j]     + q4[j].y * ef[4 * j + 1] +
                 q4[j].z * ef[4 * j + 2] + q4[j].w * ef[4 * j + 3];
#pragma unroll
        for (int off = 16; off >= 1; off >>= 1)
            p += __shfl_xor_sync(0xffffffffu, p, off);

        float mn = fmaxf(m, p);
        float sc = expf(m - mn);
        float wv = expf(p - mn);
        d = d * sc + wv;
#pragma unroll
        for (int i = 0; i < 32; ++i) ctx[i] = ctx[i] * sc + wv * ef[i];
        m = mn;
    }

    if (w >= 8) {
#pragma unroll
        for (int j = 0; j < 4; ++j) {
            ((float4*)sm_ctx[w - 8])[2 * lane + 64 * j]     = make_float4(ctx[8*j],   ctx[8*j+1], ctx[8*j+2], ctx[8*j+3]);
            ((float4*)sm_ctx[w - 8])[2 * lane + 64 * j + 1] = make_float4(ctx[8*j+4], ctx[8*j+5], ctx[8*j+6], ctx[8*j+7]);
        }
    }
    if (lane == 0) { sm_m[w] = m; sm_d[w] = d; }
    __syncthreads();
    if (w < 8) {
        float m2 = sm_m[w + 8], d2 = sm_d[w + 8];
        float mn = fmaxf(m, m2);
        float s1 = expf(m - mn), s2 = expf(m2 - mn);
        d = d * s1 + d2 * s2;
#pragma unroll
        for (int j = 0; j < 4; ++j) {
            float4 v0 = ((float4*)sm_ctx[w])[2 * lane + 64 * j];
            float4 v1 = ((float4*)sm_ctx[w])[2 * lane + 64 * j + 1];
            ctx[8*j]   = ctx[8*j]   * s1 + v0.x * s2;
            ctx[8*j+1] = ctx[8*j+1] * s1 + v0.y * s2;
            ctx[8*j+2] = ctx[8*j+2] * s1 + v0.z * s2;
            ctx[8*j+3] = ctx[8*j+3] * s1 + v0.w * s2;
            ctx[8*j+4] = ctx[8*j+4] * s1 + v1.x * s2;
            ctx[8*j+5] = ctx[8*j+5] * s1 + v1.y * s2;
            ctx[8*j+6] = ctx[8*j+6] * s1 + v1.z * s2;
            ctx[8*j+7] = ctx[8*j+7] * s1 + v1.w * s2;
        }
        m = mn;
#pragma unroll
        for (int j = 0; j < 4; ++j) {
            ((float4*)sm_ctx[w])[2 * lane + 64 * j]     = make_float4(ctx[8*j],   ctx[8*j+1], ctx[8*j+2], ctx[8*j+3]);
            ((float4*)sm_ctx[w])[2 * lane + 64 * j + 1] = make_float4(ctx[8*j+4], ctx[8*j+5], ctx[8*j+6], ctx[8*j+7]);
        }
        if (lane == 0) { sm_m[w] = m; sm_d[w] = d; }
    }
    __syncthreads();

    float mstar = sm_m[0];
#pragma unroll
    for (int ww = 1; ww < 8; ++ww) mstar = fmaxf(mstar, sm_m[ww]);
    float ew[8], dtot = 0.f;
#pragma unroll
    for (int ww = 0; ww < 8; ++ww) { ew[ww] = expf(sm_m[ww] - mstar); dtot += sm_d[ww] * ew[ww]; }
    const float inv = 1.f / dtot;

    float cx0 = 0.f, cx1 = 0.f;
#pragma unroll
    for (int ww = 0; ww < 8; ++ww) {
        float2 v = ((float2*)sm_ctx[ww])[tid];
        cx0 += v.x * ew[ww]; cx1 += v.y * ew[ww];
    }
    float* xo = xbuf + (size_t)b * XSTR + 1 + 2 * tid;
    xo[0] = cx0 * inv; xo[1] = cx1 * inv;
}

// ---------------------------------------------------------------------------
// D4: pred = h @ fc_W^T + fc_b (OUT=1); writes out[b,t] and prev_y slot.
// ---------------------------------------------------------------------------
__global__ void fc_kernel(const float* __restrict__ h,
                          const float* __restrict__ fcW,
                          const float* __restrict__ fcb,
                          float* __restrict__ out,
                          float* __restrict__ xbuf, int t)
{
    const int b = blockIdx.x;
    const int lane = threadIdx.x;
    float s = 0.f;
#pragma unroll
    for (int i = 0; i < 32; ++i) {
        int k = lane + 32 * i;
        s += h[(size_t)b * HH + k] * fcW[k];
    }
#pragma unroll
    for (int off = 16; off >= 1; off >>= 1)
        s += __shfl_xor_sync(0xffffffffu, s, off);
    if (lane == 0) {
        float p = s + fcb[0];
        out[(size_t)b * TT + t] = p;
        xbuf[(size_t)b * XSTR] = p;
    }
}

// ---------------------------------------------------------------------------
// kernel_launch: graph-capturable sequence (default stream).
// ---------------------------------------------------------------------------
extern "C" void kernel_launch(void* const* d_in, const int* in_sizes, int n_in,
                              void* d_out, int out_size)
{
    const float* src   = (const float*)d_in[0];
    const float* eWih  = (const float*)d_in[1];
    const float* eWhh  = (const float*)d_in[2];
    const float* ebih  = (const float*)d_in[3];
    const float* ebhh  = (const float*)d_in[4];
    const float* dWih  = (const float*)d_in[5];
    const float* dWhh  = (const float*)d_in[6];
    const float* dbih  = (const float*)d_in[7];
    const float* dbhh  = (const float*)d_in[8];
    const float* attnW = (const float*)d_in[9];
    const float* fcW   = (const float*)d_in[10];
    const float* fcb   = (const float*)d_in[11];
    float* out = (float*)d_out;

    float *hb, *cb, *qp, *xb, *wdp;
    __half* ench;
    cudaGetSymbolAddress((void**)&hb,   g_h);
    cudaGetSymbolAddress((void**)&cb,   g_c);
    cudaGetSymbolAddress((void**)&ench, g_ench);
    cudaGetSymbolAddress((void**)&qp,   g_qpart);
    cudaGetSymbolAddress((void**)&xb,   g_x);
    cudaGetSymbolAddress((void**)&wdp,  g_Wdih_pad);

    float* hbuf[2] = { hb, hb + BB * HH };
    float* cbuf[2] = { cb, cb + BB * HH };

    padw_kernel<<<2048, 256>>>(dWih, wdp);
    init_kernel<<<(BB * XSTR + 255) / 256, 256>>>();

    // ---- encoder: 336 steps (ntx = 2; x rows 16B-aligned) ----
    for (int t = 0; t < SS; ++t) {
        int p = t & 1;
        lstm_step_kernel<<<HH / 8, 256>>>(
            src + (size_t)t * IND, SS * IND, /*ntx=*/2, /*wk=*/IND, eWih,
            hbuf[p], eWhh, ebih, ebhh, cbuf[p],
            hbuf[1 - p], cbuf[1 - p],
            ench + (size_t)t * HH);
    }

    // ---- decoder: 96 steps (ntx = 34; x and W_ih fully padded) ----
    for (int t = 0; t < TT; ++t) {
        int p = t & 1;
        qgemm_kernel<<<128, 256>>>(hbuf[p], attnW, qp);
        attn_kernel<<<BB, 512>>>(qp, ench, xb);
        lstm_step_kernel<<<HH / 8, 256>>>(
            xb, XSTR, /*ntx=*/34, /*wk=*/XSTR, wdp,
            hbuf[p], dWhh, dbih, dbhh, cbuf[p],
            hbuf[1 - p], cbuf[1 - p],
            (__half*)nullptr);
        fc_kernel<<<BB, 32>>>(hbuf[1 - p], fcW, fcb, out, xb, t);
    }
}